// round 2
// baseline (speedup 1.0000x reference)
#include <cuda_runtime.h>
#include <cstdint>

#define B_DIM 8
#define L_DIM 4096
#define D_DIM 1024
#define N_DIM 128
#define M_TOTAL (B_DIM * L_DIM)   // 32768

// Scratch (no cudaMalloc allowed): x_proj and hs, 16 MB each.
__device__ float g_xproj[(size_t)M_TOTAL * N_DIM];
__device__ float g_hs[(size_t)M_TOTAL * N_DIM];

typedef unsigned long long u64;

__device__ __forceinline__ u64 pack2(float x, float y) {
    u64 r;
    asm("mov.b64 %0, {%1, %2};" : "=l"(r) : "f"(x), "f"(y));
    return r;
}
__device__ __forceinline__ void unpack2(u64 v, float& x, float& y) {
    asm("mov.b64 {%0, %1}, %2;" : "=f"(x), "=f"(y) : "l"(v));
}
// Packed fp32x2 FMA (sm_100+): d = a*b + c per 32-bit lane, IEEE fp32.
__device__ __forceinline__ u64 fma2(u64 a, u64 b, u64 c) {
    u64 d;
    asm("fma.rn.f32x2 %0, %1, %2, %3;" : "=l"(d) : "l"(a), "l"(b), "l"(c));
    return d;
}

// C[m][j] = sum_k A[m][k] * B[j][k]  (+ X[m][j]*Dp[j] if epilogue)
// A: M x K row-major, B: N x K row-major (both K-contiguous).
// BM=BN=128, BK=16, 256 threads, 8x8 per-thread microtile via f32x2.
__global__ void __launch_bounds__(256)
sgemm_tn(const float* __restrict__ A, const float* __restrict__ Bm,
         float* __restrict__ C, int M, int N, int K,
         const float* __restrict__ X, const float* __restrict__ Dp,
         int epilogue)
{
    __shared__ float As[16][132];
    __shared__ float Bs[16][132];

    const int tid = threadIdx.x;
    const int tx = tid & 15;
    const int ty = tid >> 4;
    const long row0 = (long)blockIdx.y * 128;
    const long col0 = (long)blockIdx.x * 128;

    u64 acc[8][4];
#pragma unroll
    for (int i = 0; i < 8; i++)
#pragma unroll
        for (int j = 0; j < 4; j++) acc[i][j] = 0ull;

    for (int kb = 0; kb < K; kb += 16) {
#pragma unroll
        for (int i = 0; i < 2; i++) {
            int idx = tid + i * 256;      // 0..511
            int r   = idx >> 2;           // row within tile (0..127)
            int c   = (idx & 3) << 2;     // k offset within tile (0,4,8,12)
            float4 va = *(const float4*)(A + (row0 + r) * (long)K + kb + c);
            As[c + 0][r] = va.x; As[c + 1][r] = va.y;
            As[c + 2][r] = va.z; As[c + 3][r] = va.w;
            float4 vb = *(const float4*)(Bm + (col0 + r) * (long)K + kb + c);
            Bs[c + 0][r] = vb.x; Bs[c + 1][r] = vb.y;
            Bs[c + 2][r] = vb.z; Bs[c + 3][r] = vb.w;
        }
        __syncthreads();

#pragma unroll
        for (int k = 0; k < 16; k++) {
            float4 a0 = *(const float4*)&As[k][ty * 8];
            float4 a1 = *(const float4*)&As[k][ty * 8 + 4];
            u64 bv0 = *(const u64*)&Bs[k][tx * 8 + 0];
            u64 bv1 = *(const u64*)&Bs[k][tx * 8 + 2];
            u64 bv2 = *(const u64*)&Bs[k][tx * 8 + 4];
            u64 bv3 = *(const u64*)&Bs[k][tx * 8 + 6];
            float a[8] = {a0.x, a0.y, a0.z, a0.w, a1.x, a1.y, a1.z, a1.w};
#pragma unroll
            for (int i = 0; i < 8; i++) {
                u64 av = pack2(a[i], a[i]);
                acc[i][0] = fma2(av, bv0, acc[i][0]);
                acc[i][1] = fma2(av, bv1, acc[i][1]);
                acc[i][2] = fma2(av, bv2, acc[i][2]);
                acc[i][3] = fma2(av, bv3, acc[i][3]);
            }
        }
        __syncthreads();
    }

#pragma unroll
    for (int i = 0; i < 8; i++) {
        long m = row0 + ty * 8 + i;
#pragma unroll
        for (int j = 0; j < 4; j++) {
            float lo, hi;
            unpack2(acc[i][j], lo, hi);
            long n = col0 + tx * 8 + 2 * j;
            if (epilogue) {
                float2 xv = *(const float2*)(X + m * (long)N + n);
                float2 dv = *(const float2*)(Dp + n);
                lo += xv.x * dv.x;
                hi += xv.y * dv.y;
            }
            float2 out; out.x = lo; out.y = hi;
            *(float2*)(C + m * (long)N + n) = out;
        }
    }
}

// Sequential scan over L per (b, n). Block = batch, thread = channel n.
// h[l] = A*h[l-1] + xproj[b,l,n]; loads are independent of h -> pipelined.
__global__ void scan_kernel(const float* __restrict__ xproj,
                            float* __restrict__ hs,
                            const float* __restrict__ log_A)
{
    int b = blockIdx.x;
    int n = threadIdx.x;
    float A = expf(log_A[n]);
    const float* src = xproj + (size_t)b * L_DIM * N_DIM + n;
    float* dst = hs + (size_t)b * L_DIM * N_DIM + n;
    float h = 0.0f;
#pragma unroll 8
    for (int l = 0; l < L_DIM; l++) {
        h = fmaf(A, h, src[(size_t)l * N_DIM]);
        dst[(size_t)l * N_DIM] = h;
    }
}

// final_state[b][n] = mean_b' xproj[b', L-1, n] (broadcast over b)
__global__ void final_state_kernel(const float* __restrict__ xproj,
                                   float* __restrict__ fs)
{
    int n = threadIdx.x;
    float s = 0.0f;
#pragma unroll
    for (int b = 0; b < B_DIM; b++)
        s += xproj[((size_t)b * L_DIM + (L_DIM - 1)) * N_DIM + n];
    s *= (1.0f / B_DIM);
#pragma unroll
    for (int b = 0; b < B_DIM; b++)
        fs[b * N_DIM + n] = s;
}

extern "C" void kernel_launch(void* const* d_in, const int* in_sizes, int n_in,
                              void* d_out, int out_size)
{
    const float* x       = (const float*)d_in[0];
    const float* B_w     = (const float*)d_in[1];
    const float* C_w     = (const float*)d_in[2];
    const float* log_A   = (const float*)d_in[3];
    const float* D_param = (const float*)d_in[4];

    float* y  = (float*)d_out;
    float* fs = y + ((size_t)out_size - (size_t)B_DIM * N_DIM);

    float* xproj = nullptr;
    float* hs    = nullptr;
    cudaGetSymbolAddress((void**)&xproj, g_xproj);
    cudaGetSymbolAddress((void**)&hs, g_hs);

    // GEMM1: x_proj = x @ B_w^T   (M=32768, N=128, K=1024)
    {
        dim3 grid(1, M_TOTAL / 128);
        sgemm_tn<<<grid, 256>>>(x, B_w, xproj, M_TOTAL, N_DIM, D_DIM,
                                nullptr, nullptr, 0);
    }

    // Scan over L
    scan_kernel<<<B_DIM, N_DIM>>>(xproj, hs, log_A);

    // GEMM2: y = hs @ C_w^T + x * D_param   (M=32768, N=1024, K=128)
    {
        dim3 grid(D_DIM / 128, M_TOTAL / 128);
        sgemm_tn<<<grid, 256>>>(hs, C_w, y, M_TOTAL, D_DIM, N_DIM,
                                x, D_param, 1);
    }

    // final_state
    final_state_kernel<<<1, N_DIM>>>(xproj, fs);
}

// round 3
// speedup vs baseline: 1.2716x; 1.2716x over previous
#include <cuda_runtime.h>
#include <cstdint>

#define B_DIM 8
#define L_DIM 4096
#define D_DIM 1024
#define N_DIM 128
#define M_TOTAL (B_DIM * L_DIM)   // 32768
#define CHUNK 128
#define NCHUNK (L_DIM / CHUNK)    // 32 per batch
#define TOT_CHUNKS (B_DIM * NCHUNK) // 256

// Scratch (no cudaMalloc allowed)
__device__ float g_xproj[(size_t)M_TOTAL * N_DIM];
__device__ float g_hs[(size_t)M_TOTAL * N_DIM];        // local scans
__device__ float g_carry[TOT_CHUNKS * N_DIM];          // per-chunk final h (local)
__device__ float g_prefix[TOT_CHUNKS * N_DIM];         // exclusive global prefix state
__device__ float g_Apow[CHUNK * N_DIM];                // A^(i+1), i-major

typedef unsigned long long u64;

__device__ __forceinline__ u64 pack2(float x, float y) {
    u64 r;
    asm("mov.b64 %0, {%1, %2};" : "=l"(r) : "f"(x), "f"(y));
    return r;
}
__device__ __forceinline__ void unpack2(u64 v, float& x, float& y) {
    asm("mov.b64 {%0, %1}, %2;" : "=f"(x), "=f"(y) : "l"(v));
}
// Packed fp32x2 FMA (sm_100+): d = a*b + c per 32-bit lane, IEEE fp32.
__device__ __forceinline__ u64 fma2(u64 a, u64 b, u64 c) {
    u64 d;
    asm("fma.rn.f32x2 %0, %1, %2, %3;" : "=l"(d) : "l"(a), "l"(b), "l"(c));
    return d;
}

// C[m][j] = sum_k Aop[m][k] * B[j][k]  (+ X[m][j]*Dp[j] if EPI)
// If FIX: Aop element at (m,k) is corrected on load:
//   a += Apow[(m&127)*128 + k] * prefix[(m>>7)*128 + k]
template<bool FIX, bool EPI>
__global__ void __launch_bounds__(256)
sgemm_tn(const float* __restrict__ A, const float* __restrict__ Bm,
         float* __restrict__ C, int N, int K,
         const float* __restrict__ X, const float* __restrict__ Dp,
         const float* __restrict__ Apow, const float* __restrict__ prefix)
{
    __shared__ float As[16][132];
    __shared__ float Bs[16][132];

    const int tid = threadIdx.x;
    const int tx = tid & 15;
    const int ty = tid >> 4;
    const long row0 = (long)blockIdx.y * 128;
    const long col0 = (long)blockIdx.x * 128;

    u64 acc[8][4];
#pragma unroll
    for (int i = 0; i < 8; i++)
#pragma unroll
        for (int j = 0; j < 4; j++) acc[i][j] = 0ull;

    for (int kb = 0; kb < K; kb += 16) {
#pragma unroll
        for (int i = 0; i < 2; i++) {
            int idx = tid + i * 256;      // 0..511
            int r   = idx >> 2;           // row within tile (0..127)
            int c   = (idx & 3) << 2;     // k offset within tile (0,4,8,12)
            long m  = row0 + r;
            float4 va = *(const float4*)(A + m * (long)K + kb + c);
            if (FIX) {
                float4 ap = *(const float4*)(Apow + (size_t)(m & 127) * N_DIM + kb + c);
                float4 pf = *(const float4*)(prefix + (size_t)(m >> 7) * N_DIM + kb + c);
                va.x = fmaf(ap.x, pf.x, va.x);
                va.y = fmaf(ap.y, pf.y, va.y);
                va.z = fmaf(ap.z, pf.z, va.z);
                va.w = fmaf(ap.w, pf.w, va.w);
            }
            As[c + 0][r] = va.x; As[c + 1][r] = va.y;
            As[c + 2][r] = va.z; As[c + 3][r] = va.w;
            float4 vb = *(const float4*)(Bm + (col0 + r) * (long)K + kb + c);
            Bs[c + 0][r] = vb.x; Bs[c + 1][r] = vb.y;
            Bs[c + 2][r] = vb.z; Bs[c + 3][r] = vb.w;
        }
        __syncthreads();

#pragma unroll
        for (int k = 0; k < 16; k++) {
            float4 a0 = *(const float4*)&As[k][ty * 8];
            float4 a1 = *(const float4*)&As[k][ty * 8 + 4];
            u64 bv0 = *(const u64*)&Bs[k][tx * 8 + 0];
            u64 bv1 = *(const u64*)&Bs[k][tx * 8 + 2];
            u64 bv2 = *(const u64*)&Bs[k][tx * 8 + 4];
            u64 bv3 = *(const u64*)&Bs[k][tx * 8 + 6];
            float a[8] = {a0.x, a0.y, a0.z, a0.w, a1.x, a1.y, a1.z, a1.w};
#pragma unroll
            for (int i = 0; i < 8; i++) {
                u64 av = pack2(a[i], a[i]);
                acc[i][0] = fma2(av, bv0, acc[i][0]);
                acc[i][1] = fma2(av, bv1, acc[i][1]);
                acc[i][2] = fma2(av, bv2, acc[i][2]);
                acc[i][3] = fma2(av, bv3, acc[i][3]);
            }
        }
        __syncthreads();
    }

#pragma unroll
    for (int i = 0; i < 8; i++) {
        long m = row0 + ty * 8 + i;
#pragma unroll
        for (int j = 0; j < 4; j++) {
            float lo, hi;
            unpack2(acc[i][j], lo, hi);
            long n = col0 + tx * 8 + 2 * j;
            if (EPI) {
                float2 xv = *(const float2*)(X + m * (long)N + n);
                float2 dv = *(const float2*)(Dp + n);
                lo += xv.x * dv.x;
                hi += xv.y * dv.y;
            }
            float2 out; out.x = lo; out.y = hi;
            *(float2*)(C + m * (long)N + n) = out;
        }
    }
}

// Local scan per 128-row chunk. grid (NCHUNK, B), block 128 (thread = channel n).
__global__ void __launch_bounds__(128)
scan_local(const float* __restrict__ xproj, float* __restrict__ hs,
           float* __restrict__ carry, const float* __restrict__ log_A)
{
    int n = threadIdx.x;
    int chunk = blockIdx.x;
    int b = blockIdx.y;
    float A = expf(log_A[n]);
    size_t base = ((size_t)b * L_DIM + (size_t)chunk * CHUNK) * N_DIM + n;
    const float* src = xproj + base;
    float* dst = hs + base;
    float h = 0.0f;
#pragma unroll 8
    for (int i = 0; i < CHUNK; i++) {
        h = fmaf(A, h, src[(size_t)i * N_DIM]);
        dst[(size_t)i * N_DIM] = h;
    }
    carry[(b * NCHUNK + chunk) * N_DIM + n] = h;
}

// Scan carries across chunks (exclusive prefix) + build Apow table (block 0).
// grid B, block 128.
__global__ void __launch_bounds__(128)
carry_scan(const float* __restrict__ carry, float* __restrict__ prefix,
           float* __restrict__ Apow, const float* __restrict__ log_A)
{
    int n = threadIdx.x;
    int b = blockIdx.x;
    float A = expf(log_A[n]);
    if (b == 0) {
        float pw = A;
#pragma unroll 8
        for (int i = 0; i < CHUNK; i++) {
            Apow[(size_t)i * N_DIM + n] = pw;   // A^(i+1)
            pw *= A;
        }
    }
    float A128 = expf(128.0f * log_A[n]);
    float h = 0.0f;
#pragma unroll
    for (int c = 0; c < NCHUNK; c++) {
        prefix[(b * NCHUNK + c) * N_DIM + n] = h;   // exclusive
        h = fmaf(A128, h, carry[(b * NCHUNK + c) * N_DIM + n]);
    }
}

// final_state[b][n] = mean_b' xproj[b', L-1, n] (broadcast over b)
__global__ void final_state_kernel(const float* __restrict__ xproj,
                                   float* __restrict__ fs)
{
    int n = threadIdx.x;
    float s = 0.0f;
#pragma unroll
    for (int b = 0; b < B_DIM; b++)
        s += xproj[((size_t)b * L_DIM + (L_DIM - 1)) * N_DIM + n];
    s *= (1.0f / B_DIM);
#pragma unroll
    for (int b = 0; b < B_DIM; b++)
        fs[b * N_DIM + n] = s;
}

extern "C" void kernel_launch(void* const* d_in, const int* in_sizes, int n_in,
                              void* d_out, int out_size)
{
    const float* x       = (const float*)d_in[0];
    const float* B_w     = (const float*)d_in[1];
    const float* C_w     = (const float*)d_in[2];
    const float* log_A   = (const float*)d_in[3];
    const float* D_param = (const float*)d_in[4];

    float* y  = (float*)d_out;
    float* fs = y + ((size_t)out_size - (size_t)B_DIM * N_DIM);

    float *xproj, *hs, *carry, *prefix, *Apow;
    cudaGetSymbolAddress((void**)&xproj, g_xproj);
    cudaGetSymbolAddress((void**)&hs, g_hs);
    cudaGetSymbolAddress((void**)&carry, g_carry);
    cudaGetSymbolAddress((void**)&prefix, g_prefix);
    cudaGetSymbolAddress((void**)&Apow, g_Apow);

    // GEMM1: x_proj = x @ B_w^T   (M=32768, N=128, K=1024)
    {
        dim3 grid(1, M_TOTAL / 128);
        sgemm_tn<false, false><<<grid, 256>>>(x, B_w, xproj, N_DIM, D_DIM,
                                              nullptr, nullptr, nullptr, nullptr);
    }

    // Chunked parallel scan
    {
        dim3 grid(NCHUNK, B_DIM);
        scan_local<<<grid, 128>>>(xproj, hs, carry, log_A);
    }
    carry_scan<<<B_DIM, 128>>>(carry, prefix, Apow, log_A);

    // GEMM2: y = (hs_local fixed-up) @ C_w^T + x * D_param
    {
        dim3 grid(D_DIM / 128, M_TOTAL / 128);
        sgemm_tn<true, true><<<grid, 256>>>(hs, C_w, y, D_DIM, N_DIM,
                                            x, D_param, Apow, prefix);
    }

    // final_state
    final_state_kernel<<<1, N_DIM>>>(xproj, fs);
}

// round 6
// speedup vs baseline: 1.9539x; 1.5366x over previous
#include <cuda_runtime.h>
#include <cuda_bf16.h>
#include <cstdint>

#define B_DIM 8
#define L_DIM 4096
#define D_DIM 1024
#define N_DIM 128
#define M_TOTAL (B_DIM * L_DIM)   // 32768
#define CHUNK 128
#define NCHUNK (L_DIM / CHUNK)    // 32
#define TOT_CHUNKS (B_DIM * NCHUNK) // 256

// Scratch (no cudaMalloc allowed)
__device__ float g_xproj[(size_t)M_TOTAL * N_DIM];
__device__ float g_hs[(size_t)M_TOTAL * N_DIM];
__device__ float g_carry[TOT_CHUNKS * N_DIM];
__device__ float g_prefix[TOT_CHUNKS * N_DIM];
__device__ float g_Apow[CHUNK * N_DIM];

typedef unsigned long long u64;
typedef uint32_t u32;

__device__ __forceinline__ u32 smem_to_u32(const void* p) {
    u32 a;
    asm("{ .reg .u64 t; cvta.to.shared.u64 t, %1; cvt.u32.u64 %0, t; }"
        : "=r"(a) : "l"(p));
    return a;
}
__device__ __forceinline__ u32 swz(u32 o) { return o ^ ((o >> 3) & 0x70); }

__device__ __forceinline__ void ldsm4(u32* r, u32 addr) {
    asm volatile("ldmatrix.sync.aligned.m8n8.x4.shared.b16 {%0,%1,%2,%3}, [%4];"
                 : "=r"(r[0]), "=r"(r[1]), "=r"(r[2]), "=r"(r[3]) : "r"(addr));
}
__device__ __forceinline__ void mma16816(float* c, const u32* a, const u32* b) {
    asm volatile("mma.sync.aligned.m16n8k16.row.col.f32.bf16.bf16.f32 "
                 "{%0,%1,%2,%3}, {%4,%5,%6,%7}, {%8,%9}, {%0,%1,%2,%3};"
                 : "+f"(c[0]), "+f"(c[1]), "+f"(c[2]), "+f"(c[3])
                 : "r"(a[0]), "r"(a[1]), "r"(a[2]), "r"(a[3]),
                   "r"(b[0]), "r"(b[1]));
}
__device__ __forceinline__ u64 pack_bf16x4(float a, float b, float c, float d) {
    __nv_bfloat162 p0 = __floats2bfloat162_rn(a, b);
    __nv_bfloat162 p1 = __floats2bfloat162_rn(c, d);
    u32 lo = *(u32*)&p0, hi = *(u32*)&p1;
    return ((u64)hi << 32) | lo;
}

// ───────── HMMA GEMM: C = A @ Bm^T (+fixup on A load / +X*Dp epilogue) ─────────
// A: M x KTOT row-major (K contig). Bm: N x KTOT row-major (K contig).
// CTA tile 128x128, 8 warps (2 m-halves x 4 n-quarters), warp tile 64x32.
// fp32 K processed in chunks of 32, bf16 split hi/lo stored interleaved in
// 128-byte SMEM rows: [hi 64B | lo 64B], SW128-swizzled -> conflict-free ldmatrix.
template<int KTOT, bool FIX, bool EPI>
__global__ void __launch_bounds__(256)
hmma_gemm(const float* __restrict__ A, const float* __restrict__ Bm,
          float* __restrict__ C, int ldc,
          const float* __restrict__ X, const float* __restrict__ Dp,
          const float* __restrict__ Apw, const float* __restrict__ pref)
{
    constexpr int KC = 32;
    constexpr int NC = KTOT / KC;
    constexpr int STAGE = 32768;      // A tile 16KB + B tile 16KB

    extern __shared__ char dsm[];
    const u32 raw = smem_to_u32(dsm);
    const u32 base = (raw + 1023u) & ~1023u;
    char* dbase = dsm + (base - raw);

    const int tid  = threadIdx.x;
    const int lane = tid & 31;
    const int warp = tid >> 5;
    const int wr = warp & 1;          // m half (64 rows)
    const int wc = warp >> 1;         // n quarter (32 cols)
    const long row0 = (long)blockIdx.y * 128;
    const long col0 = (long)blockIdx.x * 128;

    // convert-stage mapping: thread -> (row r, 16-col half)
    const int r    = tid >> 1;
    const int cf0  = (tid & 1) * 16;  // first fp32 col this thread converts
    const float* Arow = A + (row0 + r) * (long)KTOT;
    const float* Brow = Bm + (col0 + r) * (long)KTOT;

    // ldmatrix per-lane address components
    const int g  = lane >> 3;
    const int ln = lane & 7;
    const int rA = wr * 64 + (g & 1) * 8 + ln;   // + mt*16
    const int cA = (g >> 1) * 16;                // byte offset within row (+term +ks)
    const int rB = wc * 32 + (g >> 1) * 8 + ln;  // + p*16
    const int cB = (g & 1) * 16;

    float acc[4][4][4];
#pragma unroll
    for (int i = 0; i < 4; i++)
#pragma unroll
        for (int j = 0; j < 4; j++)
#pragma unroll
            for (int q = 0; q < 4; q++) acc[i][j][q] = 0.0f;

    float4 pa[4], pb[4];
#pragma unroll
    for (int q = 0; q < 4; q++) {
        pa[q] = *(const float4*)(Arow + cf0 + q * 4);
        pb[q] = *(const float4*)(Brow + cf0 + q * 4);
    }

    for (int c = 0; c < NC; c++) {
        char* bufA = dbase + (c & 1) * STAGE;
        char* bufB = bufA + 16384;
        const int kb = c * KC;

        // split fp32 -> bf16 hi/lo, store swizzled
#pragma unroll
        for (int q = 0; q < 4; q++) {
            float4 v = pa[q];
            if (FIX) {
                const int k = kb + cf0 + q * 4;
                const long m = row0 + r;
                float4 ap = *(const float4*)(Apw + (size_t)(m & 127) * N_DIM + k);
                float4 pf = *(const float4*)(pref + (size_t)(m >> 7) * N_DIM + k);
                v.x = fmaf(ap.x, pf.x, v.x);
                v.y = fmaf(ap.y, pf.y, v.y);
                v.z = fmaf(ap.z, pf.z, v.z);
                v.w = fmaf(ap.w, pf.w, v.w);
            }
            float hx = __bfloat162float(__float2bfloat16(v.x));
            float hy = __bfloat162float(__float2bfloat16(v.y));
            float hz = __bfloat162float(__float2bfloat16(v.z));
            float hw = __bfloat162float(__float2bfloat16(v.w));
            const u32 cbyte = (u32)(cf0 + q * 4) * 2;   // 0..56 within hi half
            *(u64*)(bufA + swz((u32)r * 128 + cbyte))      = pack_bf16x4(hx, hy, hz, hw);
            *(u64*)(bufA + swz((u32)r * 128 + 64 + cbyte)) =
                pack_bf16x4(v.x - hx, v.y - hy, v.z - hz, v.w - hw);

            float4 w = pb[q];
            float gx = __bfloat162float(__float2bfloat16(w.x));
            float gy = __bfloat162float(__float2bfloat16(w.y));
            float gz = __bfloat162float(__float2bfloat16(w.z));
            float gw = __bfloat162float(__float2bfloat16(w.w));
            *(u64*)(bufB + swz((u32)r * 128 + cbyte))      = pack_bf16x4(gx, gy, gz, gw);
            *(u64*)(bufB + swz((u32)r * 128 + 64 + cbyte)) =
                pack_bf16x4(w.x - gx, w.y - gy, w.z - gz, w.w - gw);
        }
        __syncthreads();

        // prefetch next chunk (latency overlapped with MMA below)
        if (c + 1 < NC) {
            const int kn = (c + 1) * KC;
#pragma unroll
            for (int q = 0; q < 4; q++) {
                pa[q] = *(const float4*)(Arow + kn + cf0 + q * 4);
                pb[q] = *(const float4*)(Brow + kn + cf0 + q * 4);
            }
        }

        // MMA phase
        const u32 ab = base + (c & 1) * STAGE;
        const u32 bb = ab + 16384;
#pragma unroll
        for (int ks = 0; ks < 2; ks++) {
            const u32 kA = (u32)(ks * 32 + cA);
            const u32 kB = (u32)(ks * 32 + cB);
            u32 ah[4][4], al[4][4], bf[2][4];
            // Ah frags
#pragma unroll
            for (int mt = 0; mt < 4; mt++)
                ldsm4(ah[mt], ab + swz((u32)(rA + mt * 16) * 128 + kA));
            // Bh frags
#pragma unroll
            for (int p = 0; p < 2; p++)
                ldsm4(bf[p], bb + swz((u32)(rB + p * 16) * 128 + kB));
            // Ah * Bh
#pragma unroll
            for (int mt = 0; mt < 4; mt++)
#pragma unroll
                for (int nt = 0; nt < 4; nt++)
                    mma16816(acc[mt][nt], ah[mt], &bf[nt >> 1][(nt & 1) * 2]);
            // Al frags, Al * Bh
#pragma unroll
            for (int mt = 0; mt < 4; mt++)
                ldsm4(al[mt], ab + swz((u32)(rA + mt * 16) * 128 + 64 + kA));
#pragma unroll
            for (int mt = 0; mt < 4; mt++)
#pragma unroll
                for (int nt = 0; nt < 4; nt++)
                    mma16816(acc[mt][nt], al[mt], &bf[nt >> 1][(nt & 1) * 2]);
            // Bl frags, Ah * Bl
#pragma unroll
            for (int p = 0; p < 2; p++)
                ldsm4(bf[p], bb + swz((u32)(rB + p * 16) * 128 + 64 + kB));
#pragma unroll
            for (int mt = 0; mt < 4; mt++)
#pragma unroll
                for (int nt = 0; nt < 4; nt++)
                    mma16816(acc[mt][nt], ah[mt], &bf[nt >> 1][(nt & 1) * 2]);
        }
        __syncthreads();
    }

    // epilogue: acc -> C (+ X*Dp)
    const int er = lane >> 2;          // 0..7
    const int ec = (lane & 3) * 2;     // 0,2,4,6
#pragma unroll
    for (int mt = 0; mt < 4; mt++) {
#pragma unroll
        for (int nt = 0; nt < 4; nt++) {
            const long m = row0 + wr * 64 + mt * 16 + er;
            const long n = col0 + wc * 32 + nt * 8 + ec;
            float2 o0 = make_float2(acc[mt][nt][0], acc[mt][nt][1]);
            float2 o1 = make_float2(acc[mt][nt][2], acc[mt][nt][3]);
            if (EPI) {
                float2 dv = *(const float2*)(Dp + n);
                float2 x0 = *(const float2*)(X + m * (long)ldc + n);
                float2 x1 = *(const float2*)(X + (m + 8) * (long)ldc + n);
                o0.x = fmaf(x0.x, dv.x, o0.x);
                o0.y = fmaf(x0.y, dv.y, o0.y);
                o1.x = fmaf(x1.x, dv.x, o1.x);
                o1.y = fmaf(x1.y, dv.y, o1.y);
            }
            *(float2*)(C + m * (long)ldc + n) = o0;
            *(float2*)(C + (m + 8) * (long)ldc + n) = o1;
        }
    }
}

// ───────────────────── scan kernels (unchanged) ─────────────────────
__global__ void __launch_bounds__(128)
scan_local(const float* __restrict__ xproj, float* __restrict__ hs,
           float* __restrict__ carry, const float* __restrict__ log_A)
{
    int n = threadIdx.x;
    int chunk = blockIdx.x;
    int b = blockIdx.y;
    float A = expf(log_A[n]);
    size_t base = ((size_t)b * L_DIM + (size_t)chunk * CHUNK) * N_DIM + n;
    const float* src = xproj + base;
    float* dst = hs + base;
    float h = 0.0f;
#pragma unroll 8
    for (int i = 0; i < CHUNK; i++) {
        h = fmaf(A, h, src[(size_t)i * N_DIM]);
        dst[(size_t)i * N_DIM] = h;
    }
    carry[(b * NCHUNK + chunk) * N_DIM + n] = h;
}

__global__ void __launch_bounds__(128)
carry_scan(const float* __restrict__ carry, float* __restrict__ prefix,
           float* __restrict__ Apow, const float* __restrict__ log_A)
{
    int n = threadIdx.x;
    int b = blockIdx.x;
    float A = expf(log_A[n]);
    if (b == 0) {
        float pw = A;
#pragma unroll 8
        for (int i = 0; i < CHUNK; i++) {
            Apow[(size_t)i * N_DIM + n] = pw;   // A^(i+1)
            pw *= A;
        }
    }
    float A128 = expf(128.0f * log_A[n]);
    float h = 0.0f;
#pragma unroll
    for (int c = 0; c < NCHUNK; c++) {
        prefix[(b * NCHUNK + c) * N_DIM + n] = h;   // exclusive
        h = fmaf(A128, h, carry[(b * NCHUNK + c) * N_DIM + n]);
    }
}

__global__ void final_state_kernel(const float* __restrict__ xproj,
                                   float* __restrict__ fs)
{
    int n = threadIdx.x;
    float s = 0.0f;
#pragma unroll
    for (int b = 0; b < B_DIM; b++)
        s += xproj[((size_t)b * L_DIM + (L_DIM - 1)) * N_DIM + n];
    s *= (1.0f / B_DIM);
#pragma unroll
    for (int b = 0; b < B_DIM; b++)
        fs[b * N_DIM + n] = s;
}

// ─────────────────────────────── launch ───────────────────────────────
extern "C" void kernel_launch(void* const* d_in, const int* in_sizes, int n_in,
                              void* d_out, int out_size)
{
    const float* x       = (const float*)d_in[0];
    const float* B_w     = (const float*)d_in[1];
    const float* C_w     = (const float*)d_in[2];
    const float* log_A   = (const float*)d_in[3];
    const float* D_param = (const float*)d_in[4];

    float* y  = (float*)d_out;
    float* fs = y + ((size_t)out_size - (size_t)B_DIM * N_DIM);

    float *xproj, *hs, *carry, *prefix, *Apow;
    cudaGetSymbolAddress((void**)&xproj, g_xproj);
    cudaGetSymbolAddress((void**)&hs, g_hs);
    cudaGetSymbolAddress((void**)&carry, g_carry);
    cudaGetSymbolAddress((void**)&prefix, g_prefix);
    cudaGetSymbolAddress((void**)&Apow, g_Apow);

    const int SMEM_BYTES = 2 * 32768 + 1024;
    cudaFuncSetAttribute(hmma_gemm<1024, false, false>,
                         cudaFuncAttributeMaxDynamicSharedMemorySize, SMEM_BYTES);
    cudaFuncSetAttribute(hmma_gemm<128, true, true>,
                         cudaFuncAttributeMaxDynamicSharedMemorySize, SMEM_BYTES);

    // GEMM1: x_proj = x @ B_w^T   (M=32768, N=128, K=1024)
    {
        dim3 grid(1, M_TOTAL / 128);
        hmma_gemm<1024, false, false><<<grid, 256, SMEM_BYTES>>>(
            x, B_w, xproj, N_DIM, nullptr, nullptr, nullptr, nullptr);
    }

    // Chunked parallel scan
    {
        dim3 grid(NCHUNK, B_DIM);
        scan_local<<<grid, 128>>>(xproj, hs, carry, log_A);
    }
    carry_scan<<<B_DIM, 128>>>(carry, prefix, Apow, log_A);

    // GEMM2: y = (hs fixed-up) @ C_w^T + x * D_param  (M=32768, N=1024, K=128)
    {
        dim3 grid(D_DIM / 128, M_TOTAL / 128);
        hmma_gemm<128, true, true><<<grid, 256, SMEM_BYTES>>>(
            hs, C_w, y, D_DIM, x, D_param, Apow, prefix);
    }

    final_state_kernel<<<1, N_DIM>>>(xproj, fs);
}

// round 7
// speedup vs baseline: 2.4832x; 1.2709x over previous
#include <cuda_runtime.h>
#include <cuda_bf16.h>
#include <cstdint>

#define B_DIM 8
#define L_DIM 4096
#define D_DIM 1024
#define N_DIM 128
#define M_TOTAL (B_DIM * L_DIM)   // 32768
#define CHUNK 128
#define NCHUNK (L_DIM / CHUNK)    // 32
#define TOT_CHUNKS (B_DIM * NCHUNK) // 256

// Scratch (no cudaMalloc allowed)
__device__ float g_xproj[(size_t)M_TOTAL * N_DIM];
__device__ float g_carry[TOT_CHUNKS * N_DIM];
__device__ float g_prefix[TOT_CHUNKS * N_DIM];
__device__ __nv_bfloat16 g_hsh[(size_t)M_TOTAL * N_DIM];
__device__ __nv_bfloat16 g_hsl[(size_t)M_TOTAL * N_DIM];
__device__ __nv_bfloat16 g_Bwh[N_DIM * D_DIM];
__device__ __nv_bfloat16 g_Bwl[N_DIM * D_DIM];
__device__ __nv_bfloat16 g_Cwh[D_DIM * N_DIM];
__device__ __nv_bfloat16 g_Cwl[D_DIM * N_DIM];

typedef unsigned long long u64;
typedef uint32_t u32;

__device__ __forceinline__ u32 smem_to_u32(const void* p) {
    u32 a;
    asm("{ .reg .u64 t; cvta.to.shared.u64 t, %1; cvt.u32.u64 %0, t; }"
        : "=r"(a) : "l"(p));
    return a;
}
__device__ __forceinline__ u32 swz(u32 o) { return o ^ ((o >> 3) & 0x70); }

__device__ __forceinline__ void ldsm4(u32* r, u32 addr) {
    asm volatile("ldmatrix.sync.aligned.m8n8.x4.shared.b16 {%0,%1,%2,%3}, [%4];"
                 : "=r"(r[0]), "=r"(r[1]), "=r"(r[2]), "=r"(r[3]) : "r"(addr));
}
__device__ __forceinline__ void mma16816(float* c, const u32* a, const u32* b) {
    asm volatile("mma.sync.aligned.m16n8k16.row.col.f32.bf16.bf16.f32 "
                 "{%0,%1,%2,%3}, {%4,%5,%6,%7}, {%8,%9}, {%0,%1,%2,%3};"
                 : "+f"(c[0]), "+f"(c[1]), "+f"(c[2]), "+f"(c[3])
                 : "r"(a[0]), "r"(a[1]), "r"(a[2]), "r"(a[3]),
                   "r"(b[0]), "r"(b[1]));
}
__device__ __forceinline__ u64 pack_bf16x4(float a, float b, float c, float d) {
    __nv_bfloat162 p0 = __floats2bfloat162_rn(a, b);
    __nv_bfloat162 p1 = __floats2bfloat162_rn(c, d);
    u32 lo = *(u32*)&p0, hi = *(u32*)&p1;
    return ((u64)hi << 32) | lo;
}
#define CP_ASYNC16(dst, src) \
    asm volatile("cp.async.cg.shared.global [%0], [%1], 16;" :: "r"(dst), "l"(src))
#define CP_COMMIT() asm volatile("cp.async.commit_group;")
#define CP_WAIT0() asm volatile("cp.async.wait_group 0;")
#define CP_WAIT1() asm volatile("cp.async.wait_group 1;")

// ───────── GEMM1: xproj = x @ B_w^T.  A (x) split in-kernel, B presplit/cp.async ─────
// CTA 128x128, 8 warps (warp tile 64x32), K chunks of 32 fp32, double buffer.
// SMEM rows 128B = [hi 64B | lo 64B], SW128.
__global__ void __launch_bounds__(256)
gemm1_hmma(const float* __restrict__ A,
           const __nv_bfloat16* __restrict__ Bwh, const __nv_bfloat16* __restrict__ Bwl,
           float* __restrict__ C)
{
    constexpr int KTOT = D_DIM;
    constexpr int KC = 32;
    constexpr int NC = KTOT / KC;      // 32
    constexpr int STAGE = 32768;       // A 16KB + B 16KB

    extern __shared__ char dsm[];
    const u32 raw = smem_to_u32(dsm);
    const u32 base = (raw + 1023u) & ~1023u;
    char* dbase = dsm + (base - raw);

    const int tid  = threadIdx.x;
    const int lane = tid & 31;
    const int warp = tid >> 5;
    const int wr = warp & 1;
    const int wc = warp >> 1;
    const long row0 = (long)blockIdx.y * 128;

    const int r   = tid >> 1;
    const int hv  = tid & 1;
    const int cf0 = hv * 16;
    const float* Arow = A + (row0 + r) * (long)KTOT;
    const __nv_bfloat16* Bsrc = (hv ? Bwl : Bwh) + (size_t)r * KTOT;

    const int g  = lane >> 3;
    const int ln = lane & 7;
    const int rA = wr * 64 + (g & 1) * 8 + ln;
    const int cA = (g >> 1) * 16;
    const int rB = wc * 32 + (g >> 1) * 8 + ln;
    const int cB = (g & 1) * 16;

    float acc[4][4][4];
#pragma unroll
    for (int i = 0; i < 4; i++)
#pragma unroll
        for (int j = 0; j < 4; j++)
#pragma unroll
            for (int q = 0; q < 4; q++) acc[i][j][q] = 0.0f;

    // prologue: prefetch A fp32 chunk0; issue B chunk0
    float4 pa[4];
#pragma unroll
    for (int q = 0; q < 4; q++) pa[q] = *(const float4*)(Arow + cf0 + q * 4);
    {
        const u32 bdst = base + 16384;
#pragma unroll
        for (int i = 0; i < 4; i++)
            CP_ASYNC16(bdst + swz((u32)r * 128 + hv * 64 + i * 16),
                       Bsrc + 0 + i * 8);
        CP_COMMIT();
    }

    for (int c = 0; c < NC; c++) {
        const int s = c & 1;
        char* bufA = dbase + s * STAGE;

        // convert A chunk c (from prefetched regs) into stage s
#pragma unroll
        for (int q = 0; q < 4; q++) {
            float4 v = pa[q];
            float hx = __bfloat162float(__float2bfloat16(v.x));
            float hy = __bfloat162float(__float2bfloat16(v.y));
            float hz = __bfloat162float(__float2bfloat16(v.z));
            float hw = __bfloat162float(__float2bfloat16(v.w));
            const u32 cbyte = (u32)(cf0 + q * 4) * 2;
            *(u64*)(bufA + swz((u32)r * 128 + cbyte))      = pack_bf16x4(hx, hy, hz, hw);
            *(u64*)(bufA + swz((u32)r * 128 + 64 + cbyte)) =
                pack_bf16x4(v.x - hx, v.y - hy, v.z - hz, v.w - hw);
        }
        // issue B chunk c+1 into other stage
        if (c + 1 < NC) {
            const u32 bdst = base + ((c + 1) & 1) * STAGE + 16384;
            const __nv_bfloat16* src = Bsrc + (c + 1) * KC;
#pragma unroll
            for (int i = 0; i < 4; i++)
                CP_ASYNC16(bdst + swz((u32)r * 128 + hv * 64 + i * 16), src + i * 8);
            CP_COMMIT();
            CP_WAIT1();
        } else {
            CP_WAIT0();
        }
        __syncthreads();

        // prefetch A fp32 chunk c+1
        if (c + 1 < NC) {
            const int kn = (c + 1) * KC;
#pragma unroll
            for (int q = 0; q < 4; q++)
                pa[q] = *(const float4*)(Arow + kn + cf0 + q * 4);
        }

        // MMA on stage s: chains AhBh, AlBh, AhBl
        const u32 ab = base + s * STAGE;
        const u32 bb = ab + 16384;
#pragma unroll
        for (int ks = 0; ks < 2; ks++) {
            const u32 kA = (u32)(ks * 32 + cA);
            const u32 kB = (u32)(ks * 32 + cB);
            u32 ah[4][4], al[4][4], bf[2][4];
#pragma unroll
            for (int mt = 0; mt < 4; mt++)
                ldsm4(ah[mt], ab + swz((u32)(rA + mt * 16) * 128 + kA));
#pragma unroll
            for (int p = 0; p < 2; p++)
                ldsm4(bf[p], bb + swz((u32)(rB + p * 16) * 128 + kB));
#pragma unroll
            for (int mt = 0; mt < 4; mt++)
#pragma unroll
                for (int nt = 0; nt < 4; nt++)
                    mma16816(acc[mt][nt], ah[mt], &bf[nt >> 1][(nt & 1) * 2]);
#pragma unroll
            for (int mt = 0; mt < 4; mt++)
                ldsm4(al[mt], ab + swz((u32)(rA + mt * 16) * 128 + 64 + kA));
#pragma unroll
            for (int mt = 0; mt < 4; mt++)
#pragma unroll
                for (int nt = 0; nt < 4; nt++)
                    mma16816(acc[mt][nt], al[mt], &bf[nt >> 1][(nt & 1) * 2]);
#pragma unroll
            for (int p = 0; p < 2; p++)
                ldsm4(bf[p], bb + swz((u32)(rB + p * 16) * 128 + 64 + kB));
#pragma unroll
            for (int mt = 0; mt < 4; mt++)
#pragma unroll
                for (int nt = 0; nt < 4; nt++)
                    mma16816(acc[mt][nt], ah[mt], &bf[nt >> 1][(nt & 1) * 2]);
        }
        __syncthreads();
    }

    // epilogue
    const int er = lane >> 2;
    const int ec = (lane & 3) * 2;
#pragma unroll
    for (int mt = 0; mt < 4; mt++)
#pragma unroll
        for (int nt = 0; nt < 4; nt++) {
            const long m = row0 + wr * 64 + mt * 16 + er;
            const long n = wc * 32 + nt * 8 + ec;
            *(float2*)(C + m * (long)N_DIM + n) = make_float2(acc[mt][nt][0], acc[mt][nt][1]);
            *(float2*)(C + (m + 8) * (long)N_DIM + n) = make_float2(acc[mt][nt][2], acc[mt][nt][3]);
        }
}

// ───────── GEMM2: y = hs @ C_w^T + x*Dp.  All operands presplit bf16, cp.async ─────
// 6 virtual chunks of K'=64 bf16: [Ah|Al|Ah] x [Bh|Bh|Bl]. 3-stage pipeline.
__global__ void __launch_bounds__(256, 2)
gemm2_hmma(const __nv_bfloat16* __restrict__ hsh, const __nv_bfloat16* __restrict__ hsl,
           const __nv_bfloat16* __restrict__ Cwh, const __nv_bfloat16* __restrict__ Cwl,
           float* __restrict__ C,
           const float* __restrict__ X, const float* __restrict__ Dp)
{
    constexpr int NVC = 6;
    constexpr int STAGE = 32768;   // A 16KB + B 16KB (128 rows x 128B)

    extern __shared__ char dsm[];
    const u32 raw = smem_to_u32(dsm);
    const u32 base = (raw + 1023u) & ~1023u;

    const int tid  = threadIdx.x;
    const int lane = tid & 31;
    const int warp = tid >> 5;
    const int wr = warp & 1;
    const int wc = warp >> 1;
    const long row0 = (long)blockIdx.y * 128;
    const long col0 = (long)blockIdx.x * 128;

    const int r2 = tid >> 1;
    const int hv = tid & 1;

    const int g  = lane >> 3;
    const int ln = lane & 7;
    const int rA = wr * 64 + (g & 1) * 8 + ln;
    const int cA = (g >> 1) * 16;
    const int rB = wc * 32 + (g >> 1) * 8 + ln;
    const int cB = (g & 1) * 16;

    float acc[4][4][4];
#pragma unroll
    for (int i = 0; i < 4; i++)
#pragma unroll
        for (int j = 0; j < 4; j++)
#pragma unroll
            for (int q = 0; q < 4; q++) acc[i][j][q] = 0.0f;

    auto issue = [&](int vc) {
        const int st = vc % 3;
        const u32 sb = base + st * STAGE;
        const int t  = vc >> 1;
        const int kk = (vc & 1) * 64;
        const __nv_bfloat16* As = (t == 1) ? hsl : hsh;
        const __nv_bfloat16* Bs = (t == 2) ? Cwl : Cwh;
        const __nv_bfloat16* asrc = As + (row0 + r2) * (long)N_DIM + kk + hv * 32;
        const __nv_bfloat16* bsrc = Bs + (col0 + r2) * (long)N_DIM + kk + hv * 32;
#pragma unroll
        for (int i = 0; i < 4; i++)
            CP_ASYNC16(sb + swz((u32)r2 * 128 + hv * 64 + i * 16), asrc + i * 8);
#pragma unroll
        for (int i = 0; i < 4; i++)
            CP_ASYNC16(sb + 16384 + swz((u32)r2 * 128 + hv * 64 + i * 16), bsrc + i * 8);
        CP_COMMIT();
    };

    issue(0);
    issue(1);

    for (int vc = 0; vc < NVC; vc++) {
        if (vc + 1 < NVC) { CP_WAIT1(); } else { CP_WAIT0(); }
        __syncthreads();
        if (vc + 2 < NVC) issue(vc + 2);

        const u32 ab = base + (vc % 3) * STAGE;
        const u32 bb = ab + 16384;
#pragma unroll
        for (int ks = 0; ks < 4; ks++) {
            const u32 kA = (u32)(ks * 32 + cA);
            const u32 kB = (u32)(ks * 32 + cB);
            u32 ah[4][4], bf[2][4];
#pragma unroll
            for (int mt = 0; mt < 4; mt++)
                ldsm4(ah[mt], ab + swz((u32)(rA + mt * 16) * 128 + kA));
#pragma unroll
            for (int p = 0; p < 2; p++)
                ldsm4(bf[p], bb + swz((u32)(rB + p * 16) * 128 + kB));
#pragma unroll
            for (int mt = 0; mt < 4; mt++)
#pragma unroll
                for (int nt = 0; nt < 4; nt++)
                    mma16816(acc[mt][nt], ah[mt], &bf[nt >> 1][(nt & 1) * 2]);
        }
        __syncthreads();
    }

    // epilogue: + X * Dp
    const int er = lane >> 2;
    const int ec = (lane & 3) * 2;
#pragma unroll
    for (int mt = 0; mt < 4; mt++)
#pragma unroll
        for (int nt = 0; nt < 4; nt++) {
            const long m = row0 + wr * 64 + mt * 16 + er;
            const long n = col0 + wc * 32 + nt * 8 + ec;
            float2 dv = *(const float2*)(Dp + n);
            float2 x0 = *(const float2*)(X + m * (long)D_DIM + n);
            float2 x1 = *(const float2*)(X + (m + 8) * (long)D_DIM + n);
            float2 o0, o1;
            o0.x = fmaf(x0.x, dv.x, acc[mt][nt][0]);
            o0.y = fmaf(x0.y, dv.y, acc[mt][nt][1]);
            o1.x = fmaf(x1.x, dv.x, acc[mt][nt][2]);
            o1.y = fmaf(x1.y, dv.y, acc[mt][nt][3]);
            *(float2*)(C + m * (long)D_DIM + n) = o0;
            *(float2*)(C + (m + 8) * (long)D_DIM + n) = o1;
        }
}

// ───────── weight presplit ─────────
__global__ void split2_kernel(const float* __restrict__ src,
                              __nv_bfloat16* __restrict__ dh,
                              __nv_bfloat16* __restrict__ dl, int n)
{
    int i = blockIdx.x * blockDim.x + threadIdx.x;
    if (i < n) {
        float v = src[i];
        __nv_bfloat16 h = __float2bfloat16(v);
        dh[i] = h;
        dl[i] = __float2bfloat16(v - __bfloat162float(h));
    }
}

// ───────── scan: 3 passes ─────────
__global__ void __launch_bounds__(128)
scan_carry(const float* __restrict__ xproj, float* __restrict__ carry,
           const float* __restrict__ log_A)
{
    int n = threadIdx.x;
    int chunk = blockIdx.x;
    int b = blockIdx.y;
    float A = expf(log_A[n]);
    const float* src = xproj + ((size_t)b * L_DIM + (size_t)chunk * CHUNK) * N_DIM + n;
    float h = 0.0f;
#pragma unroll 8
    for (int i = 0; i < CHUNK; i++)
        h = fmaf(A, h, src[(size_t)i * N_DIM]);
    carry[(b * NCHUNK + chunk) * N_DIM + n] = h;
}

__global__ void __launch_bounds__(128)
carry_scan(const float* __restrict__ carry, float* __restrict__ prefix,
           const float* __restrict__ log_A)
{
    int n = threadIdx.x;
    int b = blockIdx.x;
    float A128 = expf(128.0f * log_A[n]);
    float h = 0.0f;
#pragma unroll
    for (int c = 0; c < NCHUNK; c++) {
        prefix[(b * NCHUNK + c) * N_DIM + n] = h;   // exclusive
        h = fmaf(A128, h, carry[(b * NCHUNK + c) * N_DIM + n]);
    }
}

__global__ void __launch_bounds__(128)
scan_split(const float* __restrict__ xproj, const float* __restrict__ prefix,
           __nv_bfloat16* __restrict__ hsh, __nv_bfloat16* __restrict__ hsl,
           const float* __restrict__ log_A)
{
    int n = threadIdx.x;
    int chunk = blockIdx.x;
    int b = blockIdx.y;
    float A = expf(log_A[n]);
    size_t bo = ((size_t)b * L_DIM + (size_t)chunk * CHUNK) * N_DIM + n;
    const float* src = xproj + bo;
    float h = prefix[(b * NCHUNK + chunk) * N_DIM + n];
#pragma unroll 8
    for (int i = 0; i < CHUNK; i++) {
        h = fmaf(A, h, src[(size_t)i * N_DIM]);
        __nv_bfloat16 hb = __float2bfloat16(h);
        hsh[bo + (size_t)i * N_DIM] = hb;
        hsl[bo + (size_t)i * N_DIM] = __float2bfloat16(h - __bfloat162float(hb));
    }
}

__global__ void final_state_kernel(const float* __restrict__ xproj,
                                   float* __restrict__ fs)
{
    int n = threadIdx.x;
    float s = 0.0f;
#pragma unroll
    for (int b = 0; b < B_DIM; b++)
        s += xproj[((size_t)b * L_DIM + (L_DIM - 1)) * N_DIM + n];
    s *= (1.0f / B_DIM);
#pragma unroll
    for (int b = 0; b < B_DIM; b++)
        fs[b * N_DIM + n] = s;
}

// ─────────────────────────────── launch ───────────────────────────────
extern "C" void kernel_launch(void* const* d_in, const int* in_sizes, int n_in,
                              void* d_out, int out_size)
{
    const float* x       = (const float*)d_in[0];
    const float* B_w     = (const float*)d_in[1];
    const float* C_w     = (const float*)d_in[2];
    const float* log_A   = (const float*)d_in[3];
    const float* D_param = (const float*)d_in[4];

    float* y  = (float*)d_out;
    float* fs = y + ((size_t)out_size - (size_t)B_DIM * N_DIM);

    float *xproj, *carry, *prefix;
    __nv_bfloat16 *hsh, *hsl, *Bwh, *Bwl, *Cwh, *Cwl;
    cudaGetSymbolAddress((void**)&xproj, g_xproj);
    cudaGetSymbolAddress((void**)&carry, g_carry);
    cudaGetSymbolAddress((void**)&prefix, g_prefix);
    cudaGetSymbolAddress((void**)&hsh, g_hsh);
    cudaGetSymbolAddress((void**)&hsl, g_hsl);
    cudaGetSymbolAddress((void**)&Bwh, g_Bwh);
    cudaGetSymbolAddress((void**)&Bwl, g_Bwl);
    cudaGetSymbolAddress((void**)&Cwh, g_Cwh);
    cudaGetSymbolAddress((void**)&Cwl, g_Cwl);

    const int SMEM1 = 2 * 32768 + 1024;
    const int SMEM2 = 3 * 32768 + 1024;
    cudaFuncSetAttribute(gemm1_hmma, cudaFuncAttributeMaxDynamicSharedMemorySize, SMEM1);
    cudaFuncSetAttribute(gemm2_hmma, cudaFuncAttributeMaxDynamicSharedMemorySize, SMEM2);

    // presplit weights
    split2_kernel<<<(N_DIM * D_DIM + 255) / 256, 256>>>(B_w, Bwh, Bwl, N_DIM * D_DIM);
    split2_kernel<<<(D_DIM * N_DIM + 255) / 256, 256>>>(C_w, Cwh, Cwl, D_DIM * N_DIM);

    // GEMM1: xproj = x @ B_w^T
    {
        dim3 grid(1, M_TOTAL / 128);
        gemm1_hmma<<<grid, 256, SMEM1>>>(x, Bwh, Bwl, xproj);
    }

    // scan: carries -> prefix -> fixed split hs
    {
        dim3 grid(NCHUNK, B_DIM);
        scan_carry<<<grid, 128>>>(xproj, carry, log_A);
        carry_scan<<<B_DIM, 128>>>(carry, prefix, log_A);
        scan_split<<<grid, 128>>>(xproj, prefix, hsh, hsl, log_A);
    }

    // GEMM2: y = hs @ C_w^T + x * D_param
    {
        dim3 grid(D_DIM / 128, M_TOTAL / 128);
        gemm2_hmma<<<grid, 256, SMEM2>>>(hsh, hsl, Cwh, Cwl, y, x, D_param);
    }

    final_state_kernel<<<1, N_DIM>>>(xproj, fs);
}